// round 3
// baseline (speedup 1.0000x reference)
#include <cuda_runtime.h>
#include <cuda_bf16.h>

#define HH 64
#define WW 64
#define CC 256
#define KK 64
#define PHB 7
#define PWB 7
#define SCALE_F 0.25f

// One thread per output element (k, c, py, px). 64*256*49 = 802816 = 3136 * 256.
// 4x4 tap outer product (rows {y0l,y0h,y1l,y1h} x cols {x0l,x0h,x1l,x1h}),
// validity folded into the 1-D weights. Loads issued in two 16-wide batches
// (8 feat + 8 mask) to keep MLP high while holding register count ~40 so we
// run 6 blocks/SM. No streaming hints: the full 76MB working set fits L2 and
// should stay resident across the harness's graph replays.
__global__ __launch_bounds__(256, 6)
void masked_roialign_kernel(const float* __restrict__ feat,
                            const float* __restrict__ boxes,
                            const float* __restrict__ mask,
                            float* __restrict__ out) {
    const unsigned tid = blockIdx.x * 256u + threadIdx.x;

    // bin = tid % 49, kc = tid / 49 via mulhi (exact for tid < 2^25)
    const unsigned kc  = (unsigned)(((unsigned long long)tid * 1402438301ull) >> 36);
    const unsigned bin = tid - kc * 49u;
    const unsigned c   = kc & (CC - 1);
    const unsigned py  = (bin * 37u) >> 8;       // bin/7 for bin<49
    const unsigned px  = bin - py * 7u;

    const float* bx = boxes + (kc >> 8) * 5;
    const int   bi = (int)__ldg(bx + 0);
    const float x1 = __ldg(bx + 1) * SCALE_F;
    const float y1 = __ldg(bx + 2) * SCALE_F;
    const float x2 = __ldg(bx + 3) * SCALE_F;
    const float y2 = __ldg(bx + 4) * SCALE_F;

    const float bw = fmaxf(x2 - x1, 1.0f) * (1.0f / PWB);
    const float bh = fmaxf(y2 - y1, 1.0f) * (1.0f / PHB);

    int   rofs[4], cofs[4];
    float wy[4], wx[4];

    #pragma unroll
    for (int s = 0; s < 2; s++) {
        float v = y1 + ((float)py + ((float)s + 0.5f) * 0.5f) * bh;
        float valid = (v >= -1.0f && v <= (float)HH) ? 1.0f : 0.0f;
        float vc = fminf(fmaxf(v, 0.0f), (float)(HH - 1));
        int lo = (int)vc;
        int hi = min(lo + 1, HH - 1);
        float fr = vc - (float)lo;
        rofs[2 * s + 0] = lo * WW;
        rofs[2 * s + 1] = hi * WW;
        wy[2 * s + 0] = (1.0f - fr) * valid;
        wy[2 * s + 1] = fr * valid;
    }
    #pragma unroll
    for (int s = 0; s < 2; s++) {
        float v = x1 + ((float)px + ((float)s + 0.5f) * 0.5f) * bw;
        float valid = (v >= -1.0f && v <= (float)WW) ? 1.0f : 0.0f;
        float vc = fminf(fmaxf(v, 0.0f), (float)(WW - 1));
        int lo = (int)vc;
        int hi = min(lo + 1, WW - 1);
        float fr = vc - (float)lo;
        cofs[2 * s + 0] = lo;
        cofs[2 * s + 1] = hi;
        wx[2 * s + 0] = (1.0f - fr) * valid;
        wx[2 * s + 1] = fr * valid;
    }

    const float* f = feat + ((size_t)bi * CC + c) * (HH * WW);
    const float* m = mask + ((size_t)kc) * (HH * WW);

    float acc = 0.0f;
    // Two batches of 2 rows each: 8 feat + 8 mask loads per batch (MLP=16).
    #pragma unroll
    for (int half = 0; half < 2; half++) {
        float fv[8], mv[8];
        #pragma unroll
        for (int a = 0; a < 2; a++) {
            #pragma unroll
            for (int b = 0; b < 4; b++) {
                int idx = rofs[2 * half + a] + cofs[b];
                fv[a * 4 + b] = __ldg(f + idx);
                mv[a * 4 + b] = __ldg(m + idx);
            }
        }
        #pragma unroll
        for (int a = 0; a < 2; a++) {
            #pragma unroll
            for (int b = 0; b < 4; b++) {
                acc += (wy[2 * half + a] * wx[b]) * (fv[a * 4 + b] * mv[a * 4 + b]);
            }
        }
    }

    out[tid] = acc * 0.25f;
}

extern "C" void kernel_launch(void* const* d_in, const int* in_sizes, int n_in,
                              void* d_out, int out_size) {
    const float* feat  = (const float*)d_in[0];   // [2,256,64,64]
    const float* boxes = (const float*)d_in[1];   // [64,5]
    const float* mask  = (const float*)d_in[2];   // [64,256,64,64]
    float* out = (float*)d_out;                   // [64,256,7,7]

    const int total = KK * CC * PHB * PWB;        // 802816
    masked_roialign_kernel<<<total / 256, 256>>>(feat, boxes, mask, out);
}